// round 17
// baseline (speedup 1.0000x reference)
#include <cuda_runtime.h>
#include <cuda_bf16.h>
#include <mma.h>
#include <math.h>
#include <stdint.h>

using namespace nvcuda;

#define BATCH   32
#define ETOT    262144
#define NMAX    32768
#define K1      615
#define K2      369
#define K3      185
#define N1      32768
#define N2      (BATCH*K1)
#define N3      (BATCH*K2)
#define N4      (BATCH*K3)

#define CEILDIV(a,b) (((a)+(b)-1)/(b))

__device__ float g_buf0[(size_t)NMAX * 512];
__device__ float g_buf1[(size_t)NMAX * 512];
__device__ float g_dis[NMAX];
__device__ float g_score[NMAX];
__device__ float g_t[NMAX];
__device__ float g_gain[NMAX];
__device__ int   g_newid[NMAX];
__device__ int   g_perm[NMAX];
__device__ int   g_src[ETOT];
__device__ int   g_dst[ETOT];
__device__ float g_ew[ETOT];
__device__ float g_bnstats[1024];
__device__ int   g_icount[NMAX];
__device__ int   g_rowptr[NMAX + 1];
__device__ int   g_cursor[NMAX];
__device__ int   g_esrc[ETOT];
__device__ float g_enorm[ETOT];
__device__ int   g_blocksum[32];
__device__ int   g_blockoff[32];
__device__ __nv_bfloat16 g_aHi[(size_t)NMAX * 512];
__device__ __nv_bfloat16 g_aLo[(size_t)NMAX * 512];
__device__ __nv_bfloat16 g_w1Hi[512 * 512], g_w1Lo[512 * 512];
__device__ __nv_bfloat16 g_w2Hi[512 * 512], g_w2Lo[512 * 512];
__device__ __nv_bfloat16 g_w3Hi[256 * 512], g_w3Lo[256 * 512];
__device__ __nv_bfloat16 g_w4Hi[256 * 256], g_w4Lo[256 * 256];

__global__ void edge_init_count_kernel(const int* __restrict__ ei,
                                       int* __restrict__ src, int* __restrict__ dst,
                                       float* __restrict__ ew, int* __restrict__ cnt) {
    int e = blockIdx.x * blockDim.x + threadIdx.x;
    if (e >= ETOT) return;
    int d = ei[ETOT + e];
    src[e] = ei[e];
    dst[e] = d;
    ew[e]  = 1.0f;
    atomicAdd(&cnt[d], 1);
}

__global__ void convertA_kernel(const float4* __restrict__ A,
                                __nv_bfloat162* __restrict__ hi2,
                                __nv_bfloat162* __restrict__ lo2, int n4,
                                float* __restrict__ bnstats) {
    int i = blockIdx.x * blockDim.x + threadIdx.x;
    if (i >= n4) return;
    if (i < 1024) bnstats[i] = 0.f;
    float4 v = A[i];
    __nv_bfloat16 h0 = __float2bfloat16(v.x);
    __nv_bfloat16 h1 = __float2bfloat16(v.y);
    __nv_bfloat16 h2 = __float2bfloat16(v.z);
    __nv_bfloat16 h3 = __float2bfloat16(v.w);
    hi2[2 * i]     = __halves2bfloat162(h0, h1);
    hi2[2 * i + 1] = __halves2bfloat162(h2, h3);
    lo2[2 * i]     = __halves2bfloat162(__float2bfloat16(v.x - __bfloat162float(h0)),
                                        __float2bfloat16(v.y - __bfloat162float(h1)));
    lo2[2 * i + 1] = __halves2bfloat162(__float2bfloat16(v.z - __bfloat162float(h2)),
                                        __float2bfloat16(v.w - __bfloat162float(h3)));
}

#define W1_ELEMS (512 * 512)
#define W2_END   (2 * W1_ELEMS)
#define W3_END   (W2_END + 256 * 512)
#define W4_END   (W3_END + 256 * 256)
__global__ void convertW_all_kernel(const float* __restrict__ W1, const float* __restrict__ W2,
                                    const float* __restrict__ W3, const float* __restrict__ W4,
                                    __nv_bfloat16* w1h, __nv_bfloat16* w1l,
                                    __nv_bfloat16* w2h, __nv_bfloat16* w2l,
                                    __nv_bfloat16* w3h, __nv_bfloat16* w3l,
                                    __nv_bfloat16* w4h, __nv_bfloat16* w4l,
                                    int* __restrict__ icount) {
    int idx = blockIdx.x * blockDim.x + threadIdx.x;
    if (idx < N1) icount[idx] = 0;
    const float* W; __nv_bfloat16 *h, *l; int K, N, local;
    if (idx < W1_ELEMS)      { W = W1; h = w1h; l = w1l; K = 512; N = 512; local = idx; }
    else if (idx < W2_END)   { W = W2; h = w2h; l = w2l; K = 512; N = 512; local = idx - W1_ELEMS; }
    else if (idx < W3_END)   { W = W3; h = w3h; l = w3l; K = 512; N = 256; local = idx - W2_END; }
    else if (idx < W4_END)   { W = W4; h = w4h; l = w4l; K = 256; N = 256; local = idx - W3_END; }
    else return;
    int n = local / K, k = local - n * K;
    float v = W[k * N + n];
    __nv_bfloat16 hh = __float2bfloat16(v);
    h[local] = hh;
    l[local] = __float2bfloat16(v - __bfloat162float(hh));
}

#define TBM 128
#define TBN 128
#define TBK 32
#define WLDA 40
#define TILE_BYTES (128 * WLDA * 2)
#define TILE_ELEMS (128 * WLDA)
#define STAGE_BYTES (4 * TILE_BYTES)
#define GEMM_SMEM (2 * STAGE_BYTES)

__device__ __forceinline__ void cp16(uint32_t s, const void* g, int sz) {
    asm volatile("cp.async.cg.shared.global [%0], [%1], 16, %2;"
                 :: "r"(s), "l"(g), "r"(sz));
}

__global__ void __launch_bounds__(256, 2)
wmma_gemm_kernel(const __nv_bfloat16* __restrict__ Ahi,
                 const __nv_bfloat16* __restrict__ Alo,
                 const __nv_bfloat16* __restrict__ Bhi,
                 const __nv_bfloat16* __restrict__ Blo,
                 float* __restrict__ C, int M, int K, int N) {
    extern __shared__ __nv_bfloat16 sm[];

    const int tid = threadIdx.x;
    const int wid = tid >> 5;
    const int warpM = wid & 1;
    const int warpN = wid >> 1;
    const int mBase = blockIdx.y * TBM;
    const int nBase = blockIdx.x * TBN;

    wmma::fragment<wmma::accumulator, 16, 16, 16, float> acc[4][2];
#pragma unroll
    for (int i = 0; i < 4; i++)
#pragma unroll
        for (int j = 0; j < 2; j++) wmma::fill_fragment(acc[i][j], 0.f);

    const uint32_t sbase = (uint32_t)__cvta_generic_to_shared(sm);
    const int row = tid >> 1;
    const int q0 = (tid & 1) * 2;
    const int grow = mBase + row;
    const int nrow = nBase + row;
    const size_t aoff = (size_t)(grow < M ? grow : 0) * K;
    const size_t boff = (size_t)nrow * K;
    const int szA = (grow < M) ? 16 : 0;
    const uint32_t srow = sbase + (uint32_t)row * (WLDA * 2);

#define LOAD_STAGE(s, kc) do { \
        uint32_t s0 = srow + (uint32_t)(s) * STAGE_BYTES; \
        _Pragma("unroll") \
        for (int qq = 0; qq < 2; qq++) { \
            int q = q0 + qq; \
            cp16(s0 + q * 16,                  Ahi + aoff + (kc) + q * 8, szA); \
            cp16(s0 + q * 16 + TILE_BYTES,     Alo + aoff + (kc) + q * 8, szA); \
            cp16(s0 + q * 16 + 2 * TILE_BYTES, Bhi + boff + (kc) + q * 8, 16); \
            cp16(s0 + q * 16 + 3 * TILE_BYTES, Blo + boff + (kc) + q * 8, 16); \
        } \
    } while (0)

    LOAD_STAGE(0, 0);
    asm volatile("cp.async.commit_group;" ::: "memory");

    const int nCh = K >> 5;
    for (int ch = 0; ch < nCh; ch++) {
        if (ch + 1 < nCh) {
            LOAD_STAGE((ch + 1) & 1, (ch + 1) << 5);
            asm volatile("cp.async.commit_group;" ::: "memory");
            asm volatile("cp.async.wait_group 1;" ::: "memory");
        } else {
            asm volatile("cp.async.wait_group 0;" ::: "memory");
        }
        __syncthreads();

        const __nv_bfloat16* sb   = sm + (ch & 1) * (4 * TILE_ELEMS);
        const __nv_bfloat16* sAhi = sb;
        const __nv_bfloat16* sAlo = sb + TILE_ELEMS;
        const __nv_bfloat16* sBhi = sb + 2 * TILE_ELEMS;
        const __nv_bfloat16* sBlo = sb + 3 * TILE_ELEMS;

#pragma unroll
        for (int ks = 0; ks < TBK; ks += 16) {
            wmma::fragment<wmma::matrix_b, 16, 16, 16, __nv_bfloat16, wmma::col_major> bh[2], bl[2];
#pragma unroll
            for (int j = 0; j < 2; j++) {
                wmma::load_matrix_sync(bh[j], sBhi + (warpN * 32 + j * 16) * WLDA + ks, WLDA);
                wmma::load_matrix_sync(bl[j], sBlo + (warpN * 32 + j * 16) * WLDA + ks, WLDA);
            }
#pragma unroll
            for (int i = 0; i < 4; i++) {
                wmma::fragment<wmma::matrix_a, 16, 16, 16, __nv_bfloat16, wmma::row_major> ah, al;
                wmma::load_matrix_sync(ah, sAhi + (warpM * 64 + i * 16) * WLDA + ks, WLDA);
                wmma::load_matrix_sync(al, sAlo + (warpM * 64 + i * 16) * WLDA + ks, WLDA);
#pragma unroll
                for (int j = 0; j < 2; j++) wmma::mma_sync(acc[i][j], ah, bh[j], acc[i][j]);
#pragma unroll
                for (int j = 0; j < 2; j++) wmma::mma_sync(acc[i][j], ah, bl[j], acc[i][j]);
#pragma unroll
                for (int j = 0; j < 2; j++) wmma::mma_sync(acc[i][j], al, bh[j], acc[i][j]);
            }
        }
        __syncthreads();
    }
#undef LOAD_STAGE

#pragma unroll
    for (int i = 0; i < 4; i++) {
        int r0 = mBase + warpM * 64 + i * 16;
#pragma unroll
        for (int j = 0; j < 2; j++) {
            float* cp = C + (size_t)r0 * N + nBase + warpN * 32 + j * 16;
            wmma::store_matrix_sync(cp, acc[i][j], N, wmma::mem_row_major);
        }
    }
}

__global__ void __launch_bounds__(1024)
scan_partial_kernel(const int* __restrict__ cnt, int* __restrict__ rowptr,
                    int* __restrict__ blocksum, int n) {
    __shared__ int warpsum[32];
    const int tid = threadIdx.x;
    const int i = blockIdx.x * 1024 + tid;
    int v = (i < n) ? cnt[i] : 0;
    const int s = v;

    const int lane = tid & 31, wid = tid >> 5;
#pragma unroll
    for (int off = 1; off < 32; off <<= 1) {
        int u = __shfl_up_sync(0xffffffffu, v, off);
        if (lane >= off) v += u;
    }
    if (lane == 31) warpsum[wid] = v;
    __syncthreads();
    if (wid == 0) {
        int w = warpsum[lane];
#pragma unroll
        for (int off = 1; off < 32; off <<= 1) {
            int u = __shfl_up_sync(0xffffffffu, w, off);
            if (lane >= off) w += u;
        }
        warpsum[lane] = w;
    }
    __syncthreads();
    int excl = v - s + (wid > 0 ? warpsum[wid - 1] : 0);
    if (i < n) rowptr[i] = excl;
    if (tid == 1023) blocksum[blockIdx.x] = excl + s;
}

__global__ void scan_blocksums_kernel(const int* __restrict__ blocksum,
                                      int* __restrict__ blockoff,
                                      int* __restrict__ rowptr,
                                      int nblocks, int n) {
    const int lane = threadIdx.x;
    int v = (lane < nblocks) ? blocksum[lane] : 0;
    const int s = v;
#pragma unroll
    for (int off = 1; off < 32; off <<= 1) {
        int u = __shfl_up_sync(0xffffffffu, v, off);
        if (lane >= off) v += u;
    }
    if (lane < nblocks) blockoff[lane] = v - s;
    if (lane == 31) rowptr[n] = v;
}

__global__ void __launch_bounds__(1024)
scan_finalize_kernel(const int* __restrict__ cnt, int* __restrict__ rowptr,
                     const int* __restrict__ blockoff,
                     int* __restrict__ cursor, float* __restrict__ dis,
                     int* __restrict__ newid, int n) {
    const int i = blockIdx.x * 1024 + threadIdx.x;
    if (i >= n) return;
    int r = rowptr[i] + blockoff[blockIdx.x];
    rowptr[i] = r;
    cursor[i] = r;
    int c = cnt[i];
    dis[i] = (c > 0) ? rsqrtf((float)c) : 0.f;
    newid[i] = -1;
}

__global__ void fill_kernel(const int* __restrict__ src, const int* __restrict__ dst,
                            const float* __restrict__ ew, const float* __restrict__ dis,
                            int* __restrict__ cursor,
                            int* __restrict__ esrc, float* __restrict__ enorm) {
    int e = blockIdx.x * blockDim.x + threadIdx.x;
    if (e >= ETOT) return;
    float w = ew[e];
    if (w == 0.f) return;
    int s = src[e], d = dst[e];
    int pos = atomicAdd(&cursor[d], 1);
    esrc[pos] = s;
    enorm[pos] = dis[s] * dis[d] * w;
}

// 32 nodes per block; per-thread channel-exclusive BN partials -> 8 atomics/thread
template <int C, bool STATS>
__global__ void gather_agg_kernel(const float* __restrict__ h,
                                  const int* __restrict__ rowptr,
                                  const int* __restrict__ esrc,
                                  const float* __restrict__ enorm,
                                  const float* __restrict__ bias,
                                  float* __restrict__ out,
                                  float* __restrict__ bnstats,
                                  int n) {
    const int tid = threadIdx.x;
    const int nodeBase = blockIdx.x * 32;
    const float4 bias4 = *(const float4*)(bias + tid * 4);
    float4 sum = make_float4(0.f, 0.f, 0.f, 0.f);
    float4 sq  = make_float4(0.f, 0.f, 0.f, 0.f);

    const int nEnd = min(n, nodeBase + 32);
    for (int node = nodeBase; node < nEnd; node++) {
        float4 acc = bias4;
        int b = rowptr[node];
        const int e = rowptr[node + 1];
        for (; b + 3 < e; b += 4) {
            int s0 = esrc[b],     s1 = esrc[b + 1], s2 = esrc[b + 2], s3 = esrc[b + 3];
            float n0 = enorm[b],  n1 = enorm[b + 1], n2 = enorm[b + 2], n3 = enorm[b + 3];
            float4 v0 = *(const float4*)(h + (size_t)s0 * C + tid * 4);
            float4 v1 = *(const float4*)(h + (size_t)s1 * C + tid * 4);
            float4 v2 = *(const float4*)(h + (size_t)s2 * C + tid * 4);
            float4 v3 = *(const float4*)(h + (size_t)s3 * C + tid * 4);
            acc.x += v0.x * n0; acc.y += v0.y * n0; acc.z += v0.z * n0; acc.w += v0.w * n0;
            acc.x += v1.x * n1; acc.y += v1.y * n1; acc.z += v1.z * n1; acc.w += v1.w * n1;
            acc.x += v2.x * n2; acc.y += v2.y * n2; acc.z += v2.z * n2; acc.w += v2.w * n2;
            acc.x += v3.x * n3; acc.y += v3.y * n3; acc.z += v3.z * n3; acc.w += v3.w * n3;
        }
        for (; b < e; b++) {
            int s0 = esrc[b];
            float n0 = enorm[b];
            float4 v0 = *(const float4*)(h + (size_t)s0 * C + tid * 4);
            acc.x += v0.x * n0; acc.y += v0.y * n0; acc.z += v0.z * n0; acc.w += v0.w * n0;
        }
        *(float4*)(out + (size_t)node * C + tid * 4) = acc;
        if (STATS) {
            sum.x += acc.x; sum.y += acc.y; sum.z += acc.z; sum.w += acc.w;
            sq.x += acc.x * acc.x; sq.y += acc.y * acc.y;
            sq.z += acc.z * acc.z; sq.w += acc.w * acc.w;
        }
    }
    if (STATS) {
        const int c = tid * 4;
        atomicAdd(&bnstats[c + 0], sum.x);
        atomicAdd(&bnstats[c + 1], sum.y);
        atomicAdd(&bnstats[c + 2], sum.z);
        atomicAdd(&bnstats[c + 3], sum.w);
        atomicAdd(&bnstats[512 + c + 0], sq.x);
        atomicAdd(&bnstats[512 + c + 1], sq.y);
        atomicAdd(&bnstats[512 + c + 2], sq.z);
        atomicAdd(&bnstats[512 + c + 3], sq.w);
    }
}

__global__ void bn_dots_kernel(const float* __restrict__ h,
                               const float* __restrict__ bnstats,
                               const float* __restrict__ gma, const float* __restrict__ bta,
                               const float* __restrict__ relw, const float* __restrict__ rootw,
                               const float* __restrict__ relb,
                               float* __restrict__ t, float* __restrict__ score,
                               int n, int C) {
    int node = (blockIdx.x * blockDim.x + threadIdx.x) >> 5;
    int lane = threadIdx.x & 31;
    if (node >= n) return;
    const float* hp = h + (size_t)node * C;
    const float invn = 1.f / (float)n;
    float a = 0.f, b = 0.f;
    for (int c = lane; c < C; c += 32) {
        float mean = bnstats[c] * invn;
        float var = bnstats[512 + c] * invn - mean * mean;
        float y = tanhf((hp[c] - mean) * rsqrtf(var + 1e-5f) * gma[c] + bta[c]);
        a += y * relw[c];
        b += y * rootw[c];
    }
#pragma unroll
    for (int o = 16; o > 0; o >>= 1) {
        a += __shfl_down_sync(0xffffffffu, a, o);
        b += __shfl_down_sync(0xffffffffu, b, o);
    }
    if (lane == 0) {
        t[node] = a;
        score[node] = b + relb[0];
    }
}

template <int SZ>
__global__ void __launch_bounds__(512)
topk_kernel(const float* __restrict__ score, const float* __restrict__ t,
            const int* __restrict__ rowptr, const int* __restrict__ esrc,
            int n_per, int ksel,
            int* __restrict__ perm, float* __restrict__ gain, int* __restrict__ newid,
            int* __restrict__ icount) {
    __shared__ float sk[SZ];
    __shared__ int si[SZ];
    const int g = blockIdx.x;
    const int tid = threadIdx.x;
    for (int i = tid; i < SZ; i += 512) {
        if (i < n_per) {
            int node = g * n_per + i;
            float s = score[node];
            int b = rowptr[node];
            const int e = rowptr[node + 1];
            for (; b < e; b++) s += t[esrc[b]];
            sk[i] = s;
            si[i] = i;
        } else {
            sk[i] = -INFINITY;
            si[i] = 0x40000000 + i;
        }
    }
    __syncthreads();
    for (int kk = 2; kk <= SZ; kk <<= 1) {
        for (int j = kk >> 1; j > 0; j >>= 1) {
            for (int i = tid; i < SZ; i += 512) {
                int ixj = i ^ j;
                if (ixj > i) {
                    bool up = ((i & kk) == 0);
                    float s1 = sk[i], s2 = sk[ixj];
                    int i1 = si[i], i2 = si[ixj];
                    bool after = (s1 < s2) || (s1 == s2 && i1 > i2);
                    if (up == after) {
                        sk[i] = s2; sk[ixj] = s1;
                        si[i] = i2; si[ixj] = i1;
                    }
                }
            }
            __syncthreads();
        }
    }
    for (int r = tid; r < ksel; r += 512) {
        int old = g * n_per + si[r];
        int ng = g * ksel + r;
        perm[ng] = old;
        gain[ng] = tanhf(sk[r]);
        newid[old] = ng;
        icount[ng] = 0;
    }
}

__global__ void gather_split_kernel(const float* __restrict__ hin,
                                    __nv_bfloat16* __restrict__ hi,
                                    __nv_bfloat16* __restrict__ lo,
                                    const int* __restrict__ perm,
                                    const float* __restrict__ gain,
                                    const float* __restrict__ bnstats,
                                    const float* __restrict__ gma,
                                    const float* __restrict__ bta,
                                    float invn,
                                    int rows, int C4) {
    int idx = blockIdx.x * blockDim.x + threadIdx.x;
    if (idx >= rows * C4) return;
    int row = idx / C4;
    int c4 = idx - row * C4;
    int c = c4 * 4;
    float gn = gain[row];
    float4 v = ((const float4*)hin)[(size_t)perm[row] * C4 + c4];
    float m0 = bnstats[c + 0] * invn, m1 = bnstats[c + 1] * invn;
    float m2 = bnstats[c + 2] * invn, m3 = bnstats[c + 3] * invn;
    float r0 = rsqrtf(bnstats[512 + c + 0] * invn - m0 * m0 + 1e-5f) * gma[c + 0];
    float r1 = rsqrtf(bnstats[512 + c + 1] * invn - m1 * m1 + 1e-5f) * gma[c + 1];
    float r2 = rsqrtf(bnstats[512 + c + 2] * invn - m2 * m2 + 1e-5f) * gma[c + 2];
    float r3 = rsqrtf(bnstats[512 + c + 3] * invn - m3 * m3 + 1e-5f) * gma[c + 3];
    v.x = tanhf((v.x - m0) * r0 + bta[c + 0]) * gn;
    v.y = tanhf((v.y - m1) * r1 + bta[c + 1]) * gn;
    v.z = tanhf((v.z - m2) * r2 + bta[c + 2]) * gn;
    v.w = tanhf((v.w - m3) * r3 + bta[c + 3]) * gn;
    __nv_bfloat16 h0 = __float2bfloat16(v.x);
    __nv_bfloat16 h1 = __float2bfloat16(v.y);
    __nv_bfloat16 h2 = __float2bfloat16(v.z);
    __nv_bfloat16 h3 = __float2bfloat16(v.w);
    __nv_bfloat162* hp = (__nv_bfloat162*)(hi) + 2 * idx;
    __nv_bfloat162* lp = (__nv_bfloat162*)(lo) + 2 * idx;
    hp[0] = __halves2bfloat162(h0, h1);
    hp[1] = __halves2bfloat162(h2, h3);
    lp[0] = __halves2bfloat162(__float2bfloat16(v.x - __bfloat162float(h0)),
                               __float2bfloat16(v.y - __bfloat162float(h1)));
    lp[1] = __halves2bfloat162(__float2bfloat16(v.z - __bfloat162float(h2)),
                               __float2bfloat16(v.w - __bfloat162float(h3)));
}

__global__ void remap_count_kernel(int* __restrict__ src, int* __restrict__ dst,
                                   float* __restrict__ ew, const int* __restrict__ newid,
                                   int* __restrict__ cnt) {
    int e = blockIdx.x * blockDim.x + threadIdx.x;
    if (e >= ETOT) return;
    int ns = newid[src[e]];
    int nd = newid[dst[e]];
    bool keep = (ns >= 0) && (nd >= 0) && (ew[e] != 0.f);
    src[e] = keep ? ns : 0;
    dst[e] = keep ? nd : 0;
    ew[e] = keep ? ew[e] : 0.f;
    if (keep) atomicAdd(&cnt[nd], 1);
}

__global__ void readout_kernel(const float* __restrict__ h, float* __restrict__ out) {
    int g = blockIdx.x;
    int c = threadIdx.x;
    const float* p = h + (size_t)(g * K3) * 256 + c;
    float mx = -INFINITY, sm = 0.f;
    for (int i = 0; i < K3; i++) {
        float v = p[(size_t)i * 256];
        mx = fmaxf(mx, v);
        sm += v;
    }
    out[g * 512 + c] = mx;
    out[g * 512 + 256 + c] = sm / (float)K3;
}

extern "C" void kernel_launch(void* const* d_in, const int* in_sizes, int n_in,
                              void* d_out, int out_size) {
    const float* x    = (const float*)d_in[0];
    const int*   ei   = (const int*)d_in[1];
    const float* W1   = (const float*)d_in[2];
    const float* b1   = (const float*)d_in[3];
    const float* W2   = (const float*)d_in[4];
    const float* b2   = (const float*)d_in[5];
    const float* W3   = (const float*)d_in[6];
    const float* b3   = (const float*)d_in[7];
    const float* W4   = (const float*)d_in[8];
    const float* b4   = (const float*)d_in[9];
    const float* g1   = (const float*)d_in[10];
    const float* be1  = (const float*)d_in[11];
    const float* g2   = (const float*)d_in[12];
    const float* be2  = (const float*)d_in[13];
    const float* g3   = (const float*)d_in[14];
    const float* be3  = (const float*)d_in[15];
    const float* p1rw = (const float*)d_in[16];
    const float* p1rb = (const float*)d_in[17];
    const float* p1ow = (const float*)d_in[18];
    const float* p2rw = (const float*)d_in[19];
    const float* p2rb = (const float*)d_in[20];
    const float* p2ow = (const float*)d_in[21];
    const float* p3rw = (const float*)d_in[22];
    const float* p3rb = (const float*)d_in[23];
    const float* p3ow = (const float*)d_in[24];
    float* out = (float*)d_out;

    float *buf0, *buf1, *dis, *score, *t, *gain, *ew, *bnstats, *enorm;
    int *src, *dst, *newid, *perm, *icount, *rowptr, *cursor, *esrc, *blocksum, *blockoff;
    __nv_bfloat16 *aHi, *aLo;
    __nv_bfloat16 *w1h, *w1l, *w2h, *w2l, *w3h, *w3l, *w4h, *w4l;
    cudaGetSymbolAddress((void**)&buf0, g_buf0);
    cudaGetSymbolAddress((void**)&buf1, g_buf1);
    cudaGetSymbolAddress((void**)&dis, g_dis);
    cudaGetSymbolAddress((void**)&score, g_score);
    cudaGetSymbolAddress((void**)&t, g_t);
    cudaGetSymbolAddress((void**)&gain, g_gain);
    cudaGetSymbolAddress((void**)&ew, g_ew);
    cudaGetSymbolAddress((void**)&bnstats, g_bnstats);
    cudaGetSymbolAddress((void**)&src, g_src);
    cudaGetSymbolAddress((void**)&dst, g_dst);
    cudaGetSymbolAddress((void**)&newid, g_newid);
    cudaGetSymbolAddress((void**)&perm, g_perm);
    cudaGetSymbolAddress((void**)&icount, g_icount);
    cudaGetSymbolAddress((void**)&rowptr, g_rowptr);
    cudaGetSymbolAddress((void**)&cursor, g_cursor);
    cudaGetSymbolAddress((void**)&esrc, g_esrc);
    cudaGetSymbolAddress((void**)&enorm, g_enorm);
    cudaGetSymbolAddress((void**)&blocksum, g_blocksum);
    cudaGetSymbolAddress((void**)&blockoff, g_blockoff);
    cudaGetSymbolAddress((void**)&aHi, g_aHi);
    cudaGetSymbolAddress((void**)&aLo, g_aLo);
    cudaGetSymbolAddress((void**)&w1h, g_w1Hi);
    cudaGetSymbolAddress((void**)&w1l, g_w1Lo);
    cudaGetSymbolAddress((void**)&w2h, g_w2Hi);
    cudaGetSymbolAddress((void**)&w2l, g_w2Lo);
    cudaGetSymbolAddress((void**)&w3h, g_w3Hi);
    cudaGetSymbolAddress((void**)&w3l, g_w3Lo);
    cudaGetSymbolAddress((void**)&w4h, g_w4Hi);
    cudaGetSymbolAddress((void**)&w4l, g_w4Lo);

    cudaFuncSetAttribute(wmma_gemm_kernel,
                         cudaFuncAttributeMaxDynamicSharedMemorySize, GEMM_SMEM);

    static cudaStream_t s2 = nullptr;
    static cudaEvent_t evRoot, evW, evCSR[4], evT[3];
    if (s2 == nullptr) {
        cudaStreamCreateWithFlags(&s2, cudaStreamNonBlocking);
        cudaEventCreateWithFlags(&evRoot, cudaEventDisableTiming);
        cudaEventCreateWithFlags(&evW, cudaEventDisableTiming);
        for (int i = 0; i < 4; i++) cudaEventCreateWithFlags(&evCSR[i], cudaEventDisableTiming);
        for (int i = 0; i < 3; i++) cudaEventCreateWithFlags(&evT[i], cudaEventDisableTiming);
    }

    const int EB = CEILDIV(ETOT, 256);
    const cudaStream_t s0 = 0;

    cudaEventRecord(evRoot, s0);
    cudaStreamWaitEvent(s2, evRoot, 0);
    convertW_all_kernel<<<CEILDIV(W4_END, 256), 256, 0, s2>>>(W1, W2, W3, W4,
                                                              w1h, w1l, w2h, w2l,
                                                              w3h, w3l, w4h, w4l, icount);
    cudaEventRecord(evW, s2);
    edge_init_count_kernel<<<EB, 256, 0, s2>>>(ei, src, dst, ew, icount);

    auto csr_chain = [&](int n) {
        int nb = CEILDIV(n, 1024);
        scan_partial_kernel<<<nb, 1024, 0, s2>>>(icount, rowptr, blocksum, n);
        scan_blocksums_kernel<<<1, 32, 0, s2>>>(blocksum, blockoff, rowptr, nb, n);
        scan_finalize_kernel<<<nb, 1024, 0, s2>>>(icount, rowptr, blockoff,
                                                  cursor, dis, newid, n);
        fill_kernel<<<EB, 256, 0, s2>>>(src, dst, ew, dis, cursor, esrc, enorm);
    };
    csr_chain(N1);
    cudaEventRecord(evCSR[0], s2);

    {
        int n4 = N1 * 512 / 4;
        convertA_kernel<<<CEILDIV(n4, 256), 256, 0, s0>>>((const float4*)x,
                                                          (__nv_bfloat162*)aHi,
                                                          (__nv_bfloat162*)aLo, n4, bnstats);
    }

    auto gemm = [&](int n, int Cin, int Cout,
                    const __nv_bfloat16* wh, const __nv_bfloat16* wl) {
        wmma_gemm_kernel<<<dim3(Cout / TBN, CEILDIV(n, TBM)), 256, GEMM_SMEM, s0>>>(
            aHi, aLo, wh, wl, buf1, n, Cin, Cout);
    };
    auto agg_bn_pool = [&](int n, int C, const float* b,
                           const float* gma, const float* bta,
                           const float* rw, const float* rb, const float* ow) {
        if (C == 512)
            gather_agg_kernel<512, true><<<CEILDIV(n, 32), 128, 0, s0>>>(
                buf1, rowptr, esrc, enorm, b, buf0, bnstats, n);
        else
            gather_agg_kernel<256, true><<<CEILDIV(n, 32), 64, 0, s0>>>(
                buf1, rowptr, esrc, enorm, b, buf0, bnstats, n);
        bn_dots_kernel<<<CEILDIV(n * 32, 256), 256, 0, s0>>>(buf0, bnstats, gma, bta,
                                                             rw, ow, rb, t, score, n, C);
    };
    auto side_csr = [&](int li, int nNext) {
        cudaStreamWaitEvent(s2, evT[li], 0);
        remap_count_kernel<<<EB, 256, 0, s2>>>(src, dst, ew, newid, icount);
        csr_chain(nNext);
        cudaEventRecord(evCSR[li + 1], s2);
    };

    // ---------- Layer 1 ----------
    cudaStreamWaitEvent(s0, evW, 0);
    gemm(N1, 512, 512, w1h, w1l);
    cudaStreamWaitEvent(s0, evCSR[0], 0);
    agg_bn_pool(N1, 512, b1, g1, be1, p1rw, p1rb, p1ow);
    topk_kernel<1024><<<BATCH, 512, 0, s0>>>(score, t, rowptr, esrc, 1024, K1,
                                             perm, gain, newid, icount);
    cudaEventRecord(evT[0], s0);
    side_csr(0, N2);
    gather_split_kernel<<<CEILDIV(N2 * 128, 256), 256, 0, s0>>>(
        buf0, aHi, aLo, perm, gain, bnstats, g1, be1, 1.f / (float)N1, N2, 128);
    cudaMemsetAsync(bnstats, 0, 1024 * sizeof(float), s0);

    // ---------- Layer 2 ----------
    gemm(N2, 512, 512, w2h, w2l);
    cudaStreamWaitEvent(s0, evCSR[1], 0);
    agg_bn_pool(N2, 512, b2, g2, be2, p2rw, p2rb, p2ow);
    topk_kernel<1024><<<BATCH, 512, 0, s0>>>(score, t, rowptr, esrc, K1, K2,
                                             perm, gain, newid, icount);
    cudaEventRecord(evT[1], s0);
    side_csr(1, N3);
    gather_split_kernel<<<CEILDIV(N3 * 128, 256), 256, 0, s0>>>(
        buf0, aHi, aLo, perm, gain, bnstats, g2, be2, 1.f / (float)N2, N3, 128);
    cudaMemsetAsync(bnstats, 0, 1024 * sizeof(float), s0);

    // ---------- Layer 3 ----------
    gemm(N3, 512, 256, w3h, w3l);
    cudaStreamWaitEvent(s0, evCSR[2], 0);
    agg_bn_pool(N3, 256, b3, g3, be3, p3rw, p3rb, p3ow);
    topk_kernel<512><<<BATCH, 512, 0, s0>>>(score, t, rowptr, esrc, K2, K3,
                                            perm, gain, newid, icount);
    cudaEventRecord(evT[2], s0);
    side_csr(2, N4);
    gather_split_kernel<<<CEILDIV(N4 * 64, 256), 256, 0, s0>>>(
        buf0, aHi, aLo, perm, gain, bnstats, g3, be3, 1.f / (float)N3, N4, 64);

    // ---------- Layer 4 (no BN / pool) ----------
    gemm(N4, 256, 256, w4h, w4l);
    cudaStreamWaitEvent(s0, evCSR[3], 0);
    gather_agg_kernel<256, false><<<CEILDIV(N4, 32), 64, 0, s0>>>(
        buf1, rowptr, esrc, enorm, b4, buf0, bnstats, N4);

    // ---------- readout ----------
    readout_kernel<<<BATCH, 256, 0, s0>>>(buf0, out);
    (void)in_sizes; (void)n_in; (void)out_size;
}